// round 3
// baseline (speedup 1.0000x reference)
#include <cuda_runtime.h>
#include <math.h>

#define N_NODES 50000
#define N_EDGES 800000
#define FDIM    128
#define HEADS   4
#define RNUM    11
#define NLAYER  2
#define SCALEF  0.17677669529663687f   // 1/sqrt(32)

// ---------------- scratch (device globals; no allocation allowed) -------------
__device__ float g_h[N_NODES * FDIM];
__device__ float g_q[N_NODES * FDIM];
__device__ float g_k[N_NODES * FDIM];
__device__ float g_v[N_NODES * FDIM];
__device__ float g_rel[RNUM * FDIM];
__device__ int   g_rowptr[N_NODES + 1];
__device__ int   g_cursor[N_NODES];
__device__ int   g_epack[N_EDGES];     // src | (edge_type << 20)

// ---------------- CSR build ---------------------------------------------------
__global__ void k_zero_rowptr() {
    int i = blockIdx.x * blockDim.x + threadIdx.x;
    if (i <= N_NODES) g_rowptr[i] = 0;
}

__global__ void k_hist(const int* __restrict__ dst) {
    int e = blockIdx.x * blockDim.x + threadIdx.x;
    if (e < N_EDGES) atomicAdd(&g_rowptr[dst[e] + 1], 1);
}

// single-block inclusive scan over N_NODES+1 entries (in-place)
__global__ void k_scan() {
    __shared__ int sh[1024];
    __shared__ int s_carry;
    int tid = threadIdx.x;
    if (tid == 0) s_carry = 0;
    __syncthreads();
    const int n = N_NODES + 1;
    for (int base = 0; base < n; base += 1024) {
        int i = base + tid;
        int v = (i < n) ? g_rowptr[i] : 0;
        int c = s_carry;
        sh[tid] = v;
        __syncthreads();
        #pragma unroll
        for (int off = 1; off < 1024; off <<= 1) {
            int t = (tid >= off) ? sh[tid - off] : 0;
            __syncthreads();
            sh[tid] += t;
            __syncthreads();
        }
        if (i < n) g_rowptr[i] = sh[tid] + c;
        __syncthreads();
        if (tid == 0) s_carry = c + sh[1023];
        __syncthreads();
    }
}

__global__ void k_cursor() {
    int i = blockIdx.x * blockDim.x + threadIdx.x;
    if (i < N_NODES) g_cursor[i] = g_rowptr[i];
}

__global__ void k_scatter(const int* __restrict__ src, const int* __restrict__ dst,
                          const int* __restrict__ et) {
    int e = blockIdx.x * blockDim.x + threadIdx.x;
    if (e < N_EDGES) {
        int slot = atomicAdd(&g_cursor[dst[e]], 1);
        g_epack[slot] = src[e] | (et[e] << 20);
    }
}

// ---------------- rel projection: [11,128] @ [128,128] + b --------------------
__global__ void k_relproj(const float* __restrict__ rel_emb,
                          const float* __restrict__ We,
                          const float* __restrict__ be) {
    int r = blockIdx.x, o = threadIdx.x;     // grid (11), block 128
    float acc = be[o];
    #pragma unroll 4
    for (int f = 0; f < FDIM; f++)
        acc += rel_emb[r * FDIM + f] * We[f * FDIM + o];
    g_rel[r * FDIM + o] = acc;
}

// ---------------- QKV GEMM: C[N,128] = A[N,128] @ W[128,128] + b --------------
// BM=64, BN=128, BK=32, 256 threads, thread tile 8x4.
template <int SEL>
__global__ void __launch_bounds__(256) k_gemm(const float* __restrict__ Aext, int layer,
                                              const float* __restrict__ W,
                                              const float* __restrict__ bias) {
    const float* A = layer ? g_h : Aext;
    float* C = (SEL == 0) ? g_q : (SEL == 1) ? g_k : g_v;

    __shared__ float AsT[32][68];     // [k][row], padded
    __shared__ float Bs[32][128];     // [k][col]

    int tid = threadIdx.x;
    int ty = tid >> 5, tx = tid & 31;
    int rowBase = blockIdx.x * 64;

    float acc[8][4];
    #pragma unroll
    for (int i = 0; i < 8; i++)
        #pragma unroll
        for (int j = 0; j < 4; j++) acc[i][j] = 0.f;

    for (int k0 = 0; k0 < FDIM; k0 += 32) {
        // A tile: 64x32 = 512 float4, 2 per thread, store transposed
        #pragma unroll
        for (int t = 0; t < 2; t++) {
            int v = tid + t * 256;
            int r = v >> 3, c4 = v & 7;
            int grow = rowBase + r;
            float4 a = (grow < N_NODES)
                ? *(const float4*)(A + (size_t)grow * FDIM + k0 + c4 * 4)
                : make_float4(0.f, 0.f, 0.f, 0.f);
            AsT[c4 * 4 + 0][r] = a.x;
            AsT[c4 * 4 + 1][r] = a.y;
            AsT[c4 * 4 + 2][r] = a.z;
            AsT[c4 * 4 + 3][r] = a.w;
        }
        // B tile: 32x128 = 1024 float4, 4 per thread
        #pragma unroll
        for (int t = 0; t < 4; t++) {
            int v = tid + t * 256;
            int r = v >> 5, c4 = v & 31;
            *(float4*)(&Bs[r][c4 * 4]) = *(const float4*)(W + (k0 + r) * FDIM + c4 * 4);
        }
        __syncthreads();
        #pragma unroll
        for (int kk = 0; kk < 32; kk++) {
            float4 a0 = *(const float4*)(&AsT[kk][ty * 8]);
            float4 a1 = *(const float4*)(&AsT[kk][ty * 8 + 4]);
            float4 b  = *(const float4*)(&Bs[kk][tx * 4]);
            float ar[8] = {a0.x, a0.y, a0.z, a0.w, a1.x, a1.y, a1.z, a1.w};
            float br[4] = {b.x, b.y, b.z, b.w};
            #pragma unroll
            for (int i = 0; i < 8; i++)
                #pragma unroll
                for (int j = 0; j < 4; j++) acc[i][j] += ar[i] * br[j];
        }
        __syncthreads();
    }

    float4 bia = *(const float4*)(bias + tx * 4);
    #pragma unroll
    for (int i = 0; i < 8; i++) {
        int grow = rowBase + ty * 8 + i;
        if (grow < N_NODES) {
            float4 o;
            o.x = acc[i][0] + bia.x;
            o.y = acc[i][1] + bia.y;
            o.z = acc[i][2] + bia.z;
            o.w = acc[i][3] + bia.w;
            *(float4*)(C + (size_t)grow * FDIM + tx * 4) = o;
        }
    }
}

// ---------------- fused attention: warp per dst node, online softmax ----------
__global__ void __launch_bounds__(256) k_attn(const float* __restrict__ inputs, int layer) {
    __shared__ float s_rel[RNUM * FDIM];
    for (int i = threadIdx.x; i < RNUM * FDIM; i += blockDim.x) s_rel[i] = g_rel[i];
    __syncthreads();

    int gw = (blockIdx.x * blockDim.x + threadIdx.x) >> 5;
    int lane = threadIdx.x & 31;
    if (gw >= N_NODES) return;

    const float* hin = layer ? g_h : inputs;
    int base = gw * FDIM + lane;

    float qr[HEADS], m[HEADS], ss[HEADS], acc[HEADS];
    #pragma unroll
    for (int h = 0; h < HEADS; h++) {
        qr[h] = g_q[base + h * 32];
        m[h] = -INFINITY;
        ss[h] = 0.f;
        acc[h] = 0.f;
    }

    int e0 = g_rowptr[gw], e1 = g_rowptr[gw + 1];
    for (int e = e0; e < e1; e++) {
        int p = g_epack[e];
        int srcn = p & 0xFFFFF;
        int rel = p >> 20;
        int kb = srcn * FDIM + lane;
        int rb = rel * FDIM + lane;
        #pragma unroll
        for (int h = 0; h < HEADS; h++) {
            float ee = s_rel[rb + h * 32];
            float kk = g_k[kb + h * 32] + ee;
            float pr = qr[h] * kk;
            pr += __shfl_xor_sync(0xffffffffu, pr, 16);
            pr += __shfl_xor_sync(0xffffffffu, pr, 8);
            pr += __shfl_xor_sync(0xffffffffu, pr, 4);
            pr += __shfl_xor_sync(0xffffffffu, pr, 2);
            pr += __shfl_xor_sync(0xffffffffu, pr, 1);
            float score = pr * SCALEF;
            float nm = fmaxf(m[h], score);
            float cf = __expf(m[h] - nm);
            float w  = __expf(score - nm);
            float vv = g_v[kb + h * 32] + ee;
            ss[h]  = ss[h]  * cf + w;
            acc[h] = acc[h] * cf + w * vv;
            m[h] = nm;
        }
    }

    #pragma unroll
    for (int h = 0; h < HEADS; h++) {
        float a = acc[h] / (ss[h] + 1e-9f);
        float x = a + hin[base + h * 32];
        g_h[base + h * 32] = (x > 0.f) ? x : (__expf(x) - 1.f);
    }
}

// ---------------- output head -------------------------------------------------
__global__ void k_out(const float* __restrict__ Wout, const float* __restrict__ bout,
                      const float* __restrict__ cent, const float* __restrict__ gamma,
                      const float* __restrict__ beta, float* __restrict__ out) {
    int gw = (blockIdx.x * blockDim.x + threadIdx.x) >> 5;
    int lane = threadIdx.x & 31;
    if (gw >= N_NODES) return;
    float p = 0.f;
    #pragma unroll
    for (int i = 0; i < 4; i++)
        p += g_h[gw * FDIM + i * 32 + lane] * Wout[i * 32 + lane];
    p += __shfl_xor_sync(0xffffffffu, p, 16);
    p += __shfl_xor_sync(0xffffffffu, p, 8);
    p += __shfl_xor_sync(0xffffffffu, p, 4);
    p += __shfl_xor_sync(0xffffffffu, p, 2);
    p += __shfl_xor_sync(0xffffffffu, p, 1);
    if (lane == 0) {
        float lg = p + bout[0];
        float sc = cent[gw] * gamma[0] + beta[0];
        float r = sc * lg;
        out[gw] = (r > 0.f) ? r : 0.f;
    }
}

// ---------------- launch ------------------------------------------------------
extern "C" void kernel_launch(void* const* d_in, const int* in_sizes, int n_in,
                              void* d_out, int out_size) {
    const float* inputs  = (const float*)d_in[0];
    const int*   et      = (const int*)d_in[1];
    const int*   src     = (const int*)d_in[2];
    const int*   dst     = (const int*)d_in[3];
    const float* cent    = (const float*)d_in[4];
    const float* rel_emb = (const float*)d_in[5];
    const float* Wq      = (const float*)d_in[6];
    const float* bq      = (const float*)d_in[7];
    const float* Wk      = (const float*)d_in[8];
    const float* bk      = (const float*)d_in[9];
    const float* Wv      = (const float*)d_in[10];
    const float* bv      = (const float*)d_in[11];
    const float* We      = (const float*)d_in[12];
    const float* be      = (const float*)d_in[13];
    const float* Wout    = (const float*)d_in[14];
    const float* bout    = (const float*)d_in[15];
    const float* gamma   = (const float*)d_in[16];
    const float* beta    = (const float*)d_in[17];
    float* out = (float*)d_out;

    // CSR build (dst identical for both layers — built once per call)
    k_zero_rowptr<<<(N_NODES + 256) / 256, 256>>>();
    k_hist<<<(N_EDGES + 255) / 256, 256>>>(dst);
    k_scan<<<1, 1024>>>();
    k_cursor<<<(N_NODES + 255) / 256, 256>>>();
    k_scatter<<<(N_EDGES + 255) / 256, 256>>>(src, dst, et);

    int gemm_blocks = (N_NODES + 63) / 64;
    int attn_blocks = (N_NODES * 32 + 255) / 256;

    for (int l = 0; l < NLAYER; l++) {
        int wo = l * FDIM * FDIM, bo = l * FDIM;
        k_relproj<<<RNUM, FDIM>>>(rel_emb, We + wo, be + bo);
        k_gemm<0><<<gemm_blocks, 256>>>(inputs, l, Wq + wo, bq + bo);
        k_gemm<1><<<gemm_blocks, 256>>>(inputs, l, Wk + wo, bk + bo);
        k_gemm<2><<<gemm_blocks, 256>>>(inputs, l, Wv + wo, bv + bo);
        k_attn<<<attn_blocks, 256>>>(inputs, l);
    }

    k_out<<<attn_blocks, 256>>>(Wout, bout, cent, gamma, beta, out);
}

// round 4
// speedup vs baseline: 1.3098x; 1.3098x over previous
#include <cuda_runtime.h>
#include <math.h>

#define N_NODES 50000
#define N_EDGES 800000
#define FDIM    128
#define HEADS   4
#define RNUM    11
#define NLAYER  2
#define SCALEF  0.17677669529663687f   // 1/sqrt(32)

typedef unsigned long long ull;

// ---------------- scratch (device globals; no allocation allowed) -------------
__device__ float g_h[N_NODES * FDIM];
__device__ float g_q[N_NODES * FDIM];
__device__ float g_k[N_NODES * FDIM];
__device__ float g_v[N_NODES * FDIM];
__device__ float g_rel[RNUM * FDIM];
__device__ int   g_rowptr[N_NODES + 1];
__device__ int   g_cursor[N_NODES];
__device__ int   g_epack[N_EDGES];     // src | (edge_type << 20)

// ---------------- f32x2 helpers ----------------------------------------------
__device__ __forceinline__ ull fma2(ull a, ull b, ull c) {
    ull d;
    asm("fma.rn.f32x2 %0, %1, %2, %3;" : "=l"(d) : "l"(a), "l"(b), "l"(c));
    return d;
}
__device__ __forceinline__ ull dup2(float b) {
    ull d;
    asm("mov.b64 %0, {%1, %1};" : "=l"(d) : "f"(b));
    return d;
}
__device__ __forceinline__ float2 unpack2(ull a) {
    float2 r;
    asm("mov.b64 {%0, %1}, %2;" : "=f"(r.x), "=f"(r.y) : "l"(a));
    return r;
}

// ---------------- CSR build ---------------------------------------------------
__global__ void k_zero_rowptr() {
    int i = blockIdx.x * blockDim.x + threadIdx.x;
    if (i <= N_NODES) g_rowptr[i] = 0;
}

__global__ void k_hist(const int* __restrict__ dst) {
    int e = blockIdx.x * blockDim.x + threadIdx.x;
    if (e < N_EDGES) atomicAdd(&g_rowptr[dst[e] + 1], 1);
}

// single-block inclusive scan over N_NODES+1 entries (shfl-based)
__global__ void __launch_bounds__(1024) k_scan() {
    __shared__ int s_w[32];
    __shared__ int s_carry;
    int tid = threadIdx.x;
    int lane = tid & 31, wid = tid >> 5;
    if (tid == 0) s_carry = 0;
    __syncthreads();
    const int n = N_NODES + 1;
    for (int base = 0; base < n; base += 1024) {
        int i = base + tid;
        int v = (i < n) ? g_rowptr[i] : 0;
        #pragma unroll
        for (int off = 1; off < 32; off <<= 1) {
            int t = __shfl_up_sync(0xffffffffu, v, off);
            if (lane >= off) v += t;
        }
        if (lane == 31) s_w[wid] = v;
        __syncthreads();
        if (wid == 0) {
            int s = s_w[lane];
            #pragma unroll
            for (int off = 1; off < 32; off <<= 1) {
                int t = __shfl_up_sync(0xffffffffu, s, off);
                if (lane >= off) s += t;
            }
            s_w[lane] = s;
        }
        __syncthreads();
        int res = v + (wid > 0 ? s_w[wid - 1] : 0) + s_carry;
        if (i < n) g_rowptr[i] = res;
        __syncthreads();
        if (tid == 1023) s_carry = res;
        __syncthreads();
    }
}

__global__ void k_cursor() {
    int i = blockIdx.x * blockDim.x + threadIdx.x;
    if (i < N_NODES) g_cursor[i] = g_rowptr[i];
}

__global__ void k_scatter(const int* __restrict__ src, const int* __restrict__ dst,
                          const int* __restrict__ et) {
    int e = blockIdx.x * blockDim.x + threadIdx.x;
    if (e < N_EDGES) {
        int slot = atomicAdd(&g_cursor[dst[e]], 1);
        g_epack[slot] = src[e] | (et[e] << 20);
    }
}

// ---------------- rel projection: [11,128] @ [128,128] + b --------------------
__global__ void k_relproj(const float* __restrict__ rel_emb,
                          const float* __restrict__ We,
                          const float* __restrict__ be) {
    int r = blockIdx.x, o = threadIdx.x;     // grid (11), block 128
    float acc = be[o];
    #pragma unroll 4
    for (int f = 0; f < FDIM; f++)
        acc += rel_emb[r * FDIM + f] * We[f * FDIM + o];
    g_rel[r * FDIM + o] = acc;
}

// ---------------- QKV GEMM with f32x2: C[N,128] = A[N,128] @ W + b ------------
// BM=64, BN=128, BK=32, 256 threads, thread tile 8x4 (acc packed over row pairs)
template <int SEL>
__global__ void __launch_bounds__(256) k_gemm(const float* __restrict__ Aext, int layer,
                                              const float* __restrict__ W,
                                              const float* __restrict__ bias) {
    const float* A = layer ? g_h : Aext;
    float* C = (SEL == 0) ? g_q : (SEL == 1) ? g_k : g_v;

    __shared__ float AsT[32][68];     // [k][row], padded (68*4=272B, 16B-mult)
    __shared__ float Bs[32][128];     // [k][col]

    int tid = threadIdx.x;
    int ty = tid >> 5, tx = tid & 31;
    int rowBase = blockIdx.x * 64;

    ull accP[4][4];                   // [row-pair][col], each holds 2 fp32
    #pragma unroll
    for (int i = 0; i < 4; i++)
        #pragma unroll
        for (int j = 0; j < 4; j++) accP[i][j] = 0ull;

    for (int k0 = 0; k0 < FDIM; k0 += 32) {
        // A tile: 64x32 = 512 float4, 2 per thread, store transposed
        #pragma unroll
        for (int t = 0; t < 2; t++) {
            int v = tid + t * 256;
            int r = v >> 3, c4 = v & 7;
            int grow = rowBase + r;
            float4 a = (grow < N_NODES)
                ? *(const float4*)(A + (size_t)grow * FDIM + k0 + c4 * 4)
                : make_float4(0.f, 0.f, 0.f, 0.f);
            AsT[c4 * 4 + 0][r] = a.x;
            AsT[c4 * 4 + 1][r] = a.y;
            AsT[c4 * 4 + 2][r] = a.z;
            AsT[c4 * 4 + 3][r] = a.w;
        }
        // B tile: 32x128 = 1024 float4, 4 per thread
        #pragma unroll
        for (int t = 0; t < 4; t++) {
            int v = tid + t * 256;
            int r = v >> 5, c4 = v & 31;
            *(float4*)(&Bs[r][c4 * 4]) = *(const float4*)(W + (k0 + r) * FDIM + c4 * 4);
        }
        __syncthreads();
        #pragma unroll
        for (int kk = 0; kk < 32; kk++) {
            ulonglong2 aA = *(const ulonglong2*)(&AsT[kk][ty * 8]);
            ulonglong2 aB = *(const ulonglong2*)(&AsT[kk][ty * 8 + 4]);
            float4 b = *(const float4*)(&Bs[kk][tx * 4]);
            ull aP[4] = {aA.x, aA.y, aB.x, aB.y};
            ull bd[4] = {dup2(b.x), dup2(b.y), dup2(b.z), dup2(b.w)};
            #pragma unroll
            for (int ip = 0; ip < 4; ip++)
                #pragma unroll
                for (int j = 0; j < 4; j++)
                    accP[ip][j] = fma2(aP[ip], bd[j], accP[ip][j]);
        }
        __syncthreads();
    }

    float4 bia = *(const float4*)(bias + tx * 4);
    #pragma unroll
    for (int ip = 0; ip < 4; ip++) {
        float2 c0 = unpack2(accP[ip][0]);
        float2 c1 = unpack2(accP[ip][1]);
        float2 c2 = unpack2(accP[ip][2]);
        float2 c3 = unpack2(accP[ip][3]);
        int r0 = rowBase + ty * 8 + 2 * ip;
        if (r0 < N_NODES) {
            float4 o = {c0.x + bia.x, c1.x + bia.y, c2.x + bia.z, c3.x + bia.w};
            *(float4*)(C + (size_t)r0 * FDIM + tx * 4) = o;
        }
        int r1 = r0 + 1;
        if (r1 < N_NODES) {
            float4 o = {c0.y + bia.x, c1.y + bia.y, c2.y + bia.z, c3.y + bia.w};
            *(float4*)(C + (size_t)r1 * FDIM + tx * 4) = o;
        }
    }
}

// ---------------- fused attention: warp per dst node, 8 lanes per head --------
// lane l owns features [4l, 4l+4); head h = l>>3; dot reduces over 8 lanes
__global__ void __launch_bounds__(256) k_attn(const float* __restrict__ inputs, int layer) {
    __shared__ float4 s_rel[RNUM * 32];
    for (int i = threadIdx.x; i < RNUM * 32; i += 256)
        s_rel[i] = ((const float4*)g_rel)[i];
    __syncthreads();

    int gw = (blockIdx.x * 256 + threadIdx.x) >> 5;
    int lane = threadIdx.x & 31;
    if (gw >= N_NODES) return;

    const float* hin = layer ? g_h : inputs;
    const float4* k4 = (const float4*)g_k;
    const float4* v4 = (const float4*)g_v;
    int idx = gw * 32 + lane;

    float4 qr = ((const float4*)g_q)[idx];
    float m = -INFINITY, ss = 0.f;
    float4 acc = make_float4(0.f, 0.f, 0.f, 0.f);

    int e0 = g_rowptr[gw], e1 = g_rowptr[gw + 1];
    #pragma unroll 2
    for (int e = e0; e < e1; e++) {
        int p = g_epack[e];
        int sidx = (p & 0xFFFFF) * 32 + lane;
        float4 rel = s_rel[(p >> 20) * 32 + lane];
        float4 kk = k4[sidx];
        kk.x += rel.x; kk.y += rel.y; kk.z += rel.z; kk.w += rel.w;
        float pr = qr.x * kk.x + qr.y * kk.y + qr.z * kk.z + qr.w * kk.w;
        pr += __shfl_xor_sync(0xffffffffu, pr, 4);
        pr += __shfl_xor_sync(0xffffffffu, pr, 2);
        pr += __shfl_xor_sync(0xffffffffu, pr, 1);
        float score = pr * SCALEF;
        float nm = fmaxf(m, score);
        float cf = __expf(m - nm);
        float w  = __expf(score - nm);
        float4 vv = v4[sidx];
        vv.x += rel.x; vv.y += rel.y; vv.z += rel.z; vv.w += rel.w;
        ss = ss * cf + w;
        acc.x = acc.x * cf + w * vv.x;
        acc.y = acc.y * cf + w * vv.y;
        acc.z = acc.z * cf + w * vv.z;
        acc.w = acc.w * cf + w * vv.w;
        m = nm;
    }

    float inv = 1.f / (ss + 1e-9f);
    float4 hi = ((const float4*)hin)[idx];
    float4 x;
    x.x = acc.x * inv + hi.x;
    x.y = acc.y * inv + hi.y;
    x.z = acc.z * inv + hi.z;
    x.w = acc.w * inv + hi.w;
    x.x = (x.x > 0.f) ? x.x : (__expf(x.x) - 1.f);
    x.y = (x.y > 0.f) ? x.y : (__expf(x.y) - 1.f);
    x.z = (x.z > 0.f) ? x.z : (__expf(x.z) - 1.f);
    x.w = (x.w > 0.f) ? x.w : (__expf(x.w) - 1.f);
    ((float4*)g_h)[idx] = x;
}

// ---------------- output head -------------------------------------------------
__global__ void k_out(const float* __restrict__ Wout, const float* __restrict__ bout,
                      const float* __restrict__ cent, const float* __restrict__ gamma,
                      const float* __restrict__ beta, float* __restrict__ out) {
    int gw = (blockIdx.x * blockDim.x + threadIdx.x) >> 5;
    int lane = threadIdx.x & 31;
    if (gw >= N_NODES) return;
    float4 h4 = ((const float4*)g_h)[gw * 32 + lane];
    float4 w4 = ((const float4*)Wout)[lane];
    float p = h4.x * w4.x + h4.y * w4.y + h4.z * w4.z + h4.w * w4.w;
    p += __shfl_xor_sync(0xffffffffu, p, 16);
    p += __shfl_xor_sync(0xffffffffu, p, 8);
    p += __shfl_xor_sync(0xffffffffu, p, 4);
    p += __shfl_xor_sync(0xffffffffu, p, 2);
    p += __shfl_xor_sync(0xffffffffu, p, 1);
    if (lane == 0) {
        float lg = p + bout[0];
        float sc = cent[gw] * gamma[0] + beta[0];
        float r = sc * lg;
        out[gw] = (r > 0.f) ? r : 0.f;
    }
}

// ---------------- launch ------------------------------------------------------
extern "C" void kernel_launch(void* const* d_in, const int* in_sizes, int n_in,
                              void* d_out, int out_size) {
    const float* inputs  = (const float*)d_in[0];
    const int*   et      = (const int*)d_in[1];
    const int*   src     = (const int*)d_in[2];
    const int*   dst     = (const int*)d_in[3];
    const float* cent    = (const float*)d_in[4];
    const float* rel_emb = (const float*)d_in[5];
    const float* Wq      = (const float*)d_in[6];
    const float* bq      = (const float*)d_in[7];
    const float* Wk      = (const float*)d_in[8];
    const float* bk      = (const float*)d_in[9];
    const float* Wv      = (const float*)d_in[10];
    const float* bv      = (const float*)d_in[11];
    const float* We      = (const float*)d_in[12];
    const float* be      = (const float*)d_in[13];
    const float* Wout    = (const float*)d_in[14];
    const float* bout    = (const float*)d_in[15];
    const float* gamma   = (const float*)d_in[16];
    const float* beta    = (const float*)d_in[17];
    float* out = (float*)d_out;

    // CSR build (dst identical for both layers — built once per call)
    k_zero_rowptr<<<(N_NODES + 256) / 256, 256>>>();
    k_hist<<<(N_EDGES + 255) / 256, 256>>>(dst);
    k_scan<<<1, 1024>>>();
    k_cursor<<<(N_NODES + 255) / 256, 256>>>();
    k_scatter<<<(N_EDGES + 255) / 256, 256>>>(src, dst, et);

    int gemm_blocks = (N_NODES + 63) / 64;
    int attn_blocks = (N_NODES * 32 + 255) / 256;

    for (int l = 0; l < NLAYER; l++) {
        int wo = l * FDIM * FDIM, bo = l * FDIM;
        k_relproj<<<RNUM, FDIM>>>(rel_emb, We + wo, be + bo);
        k_gemm<0><<<gemm_blocks, 256>>>(inputs, l, Wq + wo, bq + bo);
        k_gemm<1><<<gemm_blocks, 256>>>(inputs, l, Wk + wo, bk + bo);
        k_gemm<2><<<gemm_blocks, 256>>>(inputs, l, Wv + wo, bv + bo);
        k_attn<<<attn_blocks, 256>>>(inputs, l);
    }

    k_out<<<attn_blocks, 256>>>(Wout, bout, cent, gamma, beta, out);
}

// round 5
// speedup vs baseline: 2.1678x; 1.6551x over previous
#include <cuda_runtime.h>
#include <math.h>

#define N_NODES 50000
#define N_EDGES 800000
#define FDIM    128
#define HEADS   4
#define RNUM    11
#define NLAYER  2
#define SCALEF  0.17677669529663687f            // 1/sqrt(32)
#define SCALE2F (0.17677669529663687f * 1.4426950408889634f)   // *log2(e)

typedef unsigned long long ull;

// ---------------- scratch (device globals; no allocation allowed) -------------
__device__ float g_h[N_NODES * FDIM];
__device__ float g_q[N_NODES * FDIM];
__device__ float g_kv[N_NODES * 2 * FDIM];     // per node: 128 k floats, 128 v floats
__device__ float g_rel[NLAYER * RNUM * FDIM];
__device__ int   g_rowptr[N_NODES + 1];
__device__ int   g_cursor[N_NODES];
__device__ int   g_epack[N_EDGES];             // src | (edge_type << 20)

// ---------------- f32x2 helpers ----------------------------------------------
__device__ __forceinline__ ull fma2(ull a, ull b, ull c) {
    ull d;
    asm("fma.rn.f32x2 %0, %1, %2, %3;" : "=l"(d) : "l"(a), "l"(b), "l"(c));
    return d;
}
__device__ __forceinline__ ull dup2(float b) {
    ull d;
    asm("mov.b64 %0, {%1, %1};" : "=l"(d) : "f"(b));
    return d;
}
__device__ __forceinline__ float2 unpack2(ull a) {
    float2 r;
    asm("mov.b64 {%0, %1}, %2;" : "=f"(r.x), "=f"(r.y) : "l"(a));
    return r;
}

// ---------------- CSR build ---------------------------------------------------
__global__ void k_zero_rowptr() {
    int i = blockIdx.x * blockDim.x + threadIdx.x;
    if (i <= N_NODES) g_rowptr[i] = 0;
}

__global__ void k_hist(const int* __restrict__ dst) {
    int e = blockIdx.x * blockDim.x + threadIdx.x;
    if (e < N_EDGES) atomicAdd(&g_rowptr[dst[e] + 1], 1);
}

// single-block inclusive scan over N_NODES+1 entries; also seeds cursor
__global__ void __launch_bounds__(1024) k_scan() {
    __shared__ int s_w[32];
    __shared__ int s_carry;
    int tid = threadIdx.x;
    int lane = tid & 31, wid = tid >> 5;
    if (tid == 0) s_carry = 0;
    __syncthreads();
    const int n = N_NODES + 1;
    for (int base = 0; base < n; base += 1024) {
        int i = base + tid;
        int v = (i < n) ? g_rowptr[i] : 0;
        #pragma unroll
        for (int off = 1; off < 32; off <<= 1) {
            int t = __shfl_up_sync(0xffffffffu, v, off);
            if (lane >= off) v += t;
        }
        if (lane == 31) s_w[wid] = v;
        __syncthreads();
        if (wid == 0) {
            int s = s_w[lane];
            #pragma unroll
            for (int off = 1; off < 32; off <<= 1) {
                int t = __shfl_up_sync(0xffffffffu, s, off);
                if (lane >= off) s += t;
            }
            s_w[lane] = s;
        }
        __syncthreads();
        int res = v + (wid > 0 ? s_w[wid - 1] : 0) + s_carry;
        if (i < n) g_rowptr[i] = res;
        if (i < N_NODES) g_cursor[i] = res;
        __syncthreads();
        if (tid == 1023) s_carry = res;
        __syncthreads();
    }
}

__global__ void k_scatter(const int* __restrict__ src, const int* __restrict__ dst,
                          const int* __restrict__ et) {
    int e = blockIdx.x * blockDim.x + threadIdx.x;
    if (e < N_EDGES) {
        int slot = atomicAdd(&g_cursor[dst[e]], 1);
        g_epack[slot] = src[e] | (et[e] << 20);
    }
}

// ---------------- rel projection, both layers: [11,128] @ [128,128] + b -------
__global__ void k_relproj(const float* __restrict__ rel_emb,
                          const float* __restrict__ We,
                          const float* __restrict__ be) {
    int r = blockIdx.x % RNUM, l = blockIdx.x / RNUM;
    int o = threadIdx.x;
    const float* W = We + l * FDIM * FDIM;
    float acc = be[l * FDIM + o];
    #pragma unroll 4
    for (int f = 0; f < FDIM; f++)
        acc += rel_emb[r * FDIM + f] * W[f * FDIM + o];
    g_rel[(l * RNUM + r) * FDIM + o] = acc;
}

// ---------------- QKV GEMM with f32x2: C[N,128] = A[N,128] @ W + b ------------
// BM=64, BN=128, BK=32, 256 threads, thread tile 8x4 (acc packed over row pairs)
// SEL 0 -> g_q (stride 128); SEL 1 -> g_kv+0 (stride 256); SEL 2 -> g_kv+128
template <int SEL>
__global__ void __launch_bounds__(256) k_gemm(const float* __restrict__ Aext, int layer,
                                              const float* __restrict__ W,
                                              const float* __restrict__ bias) {
    const float* A = layer ? g_h : Aext;
    float* C = (SEL == 0) ? g_q : (SEL == 1) ? g_kv : (g_kv + FDIM);
    const int CSTRIDE = (SEL == 0) ? FDIM : 2 * FDIM;

    __shared__ float AsT[32][68];     // [k][row], padded (272B = 17*16B)
    __shared__ float Bs[32][128];     // [k][col]

    int tid = threadIdx.x;
    int ty = tid >> 5, tx = tid & 31;
    int rowBase = blockIdx.x * 64;

    ull accP[4][4];
    #pragma unroll
    for (int i = 0; i < 4; i++)
        #pragma unroll
        for (int j = 0; j < 4; j++) accP[i][j] = 0ull;

    for (int k0 = 0; k0 < FDIM; k0 += 32) {
        #pragma unroll
        for (int t = 0; t < 2; t++) {
            int v = tid + t * 256;
            int r = v >> 3, c4 = v & 7;
            int grow = rowBase + r;
            float4 a = (grow < N_NODES)
                ? *(const float4*)(A + (size_t)grow * FDIM + k0 + c4 * 4)
                : make_float4(0.f, 0.f, 0.f, 0.f);
            AsT[c4 * 4 + 0][r] = a.x;
            AsT[c4 * 4 + 1][r] = a.y;
            AsT[c4 * 4 + 2][r] = a.z;
            AsT[c4 * 4 + 3][r] = a.w;
        }
        #pragma unroll
        for (int t = 0; t < 4; t++) {
            int v = tid + t * 256;
            int r = v >> 5, c4 = v & 31;
            *(float4*)(&Bs[r][c4 * 4]) = *(const float4*)(W + (k0 + r) * FDIM + c4 * 4);
        }
        __syncthreads();
        #pragma unroll
        for (int kk = 0; kk < 32; kk++) {
            ulonglong2 aA = *(const ulonglong2*)(&AsT[kk][ty * 8]);
            ulonglong2 aB = *(const ulonglong2*)(&AsT[kk][ty * 8 + 4]);
            float4 b = *(const float4*)(&Bs[kk][tx * 4]);
            ull aP[4] = {aA.x, aA.y, aB.x, aB.y};
            ull bd[4] = {dup2(b.x), dup2(b.y), dup2(b.z), dup2(b.w)};
            #pragma unroll
            for (int ip = 0; ip < 4; ip++)
                #pragma unroll
                for (int j = 0; j < 4; j++)
                    accP[ip][j] = fma2(aP[ip], bd[j], accP[ip][j]);
        }
        __syncthreads();
    }

    float4 bia = *(const float4*)(bias + tx * 4);
    #pragma unroll
    for (int ip = 0; ip < 4; ip++) {
        float2 c0 = unpack2(accP[ip][0]);
        float2 c1 = unpack2(accP[ip][1]);
        float2 c2 = unpack2(accP[ip][2]);
        float2 c3 = unpack2(accP[ip][3]);
        int r0 = rowBase + ty * 8 + 2 * ip;
        if (r0 < N_NODES) {
            float4 o = {c0.x + bia.x, c1.x + bia.y, c2.x + bia.z, c3.x + bia.w};
            *(float4*)(C + (size_t)r0 * CSTRIDE + tx * 4) = o;
        }
        int r1 = r0 + 1;
        if (r1 < N_NODES) {
            float4 o = {c0.y + bia.x, c1.y + bia.y, c2.y + bia.z, c3.y + bia.w};
            *(float4*)(C + (size_t)r1 * CSTRIDE + tx * 4) = o;
        }
    }
}

// ---------------- fused attention: warp per dst node, 8 lanes per head --------
// lane l owns features [4l, 4l+4); softmax kept in base-2 exponent domain.
// LAST layer also computes the output head (p = h . Wout, relu(scale * p)).
template <int LAYER>
__global__ void __launch_bounds__(256) k_attn(const float* __restrict__ inputs,
                                              const float* __restrict__ Wout,
                                              const float* __restrict__ bout,
                                              const float* __restrict__ cent,
                                              const float* __restrict__ gamma,
                                              const float* __restrict__ beta,
                                              float* __restrict__ out) {
    __shared__ float4 s_rel[RNUM * 32];
    {
        const float4* rel4 = (const float4*)(g_rel + LAYER * RNUM * FDIM);
        for (int i = threadIdx.x; i < RNUM * 32; i += 256) s_rel[i] = rel4[i];
    }
    __syncthreads();

    int gw = (blockIdx.x * 256 + threadIdx.x) >> 5;
    int lane = threadIdx.x & 31;
    if (gw >= N_NODES) return;

    const float* hin = LAYER ? g_h : inputs;
    const float4* kv4 = (const float4*)g_kv;
    int idx = gw * 32 + lane;

    float4 qr = ((const float4*)g_q)[idx];
    float m = -INFINITY, ss = 0.f;
    float4 acc = make_float4(0.f, 0.f, 0.f, 0.f);

    int e0 = g_rowptr[gw], e1 = g_rowptr[gw + 1];

    float4 pk, pv, pr4;
    if (e0 < e1) {
        int p = g_epack[e0];
        int si = (p & 0xFFFFF) * 64 + lane;
        pk = kv4[si];
        pv = kv4[si + 32];
        pr4 = s_rel[(p >> 20) * 32 + lane];
    }

    for (int e = e0; e < e1; e++) {
        float4 kk = pk, vv = pv, rel = pr4;
        if (e + 1 < e1) {
            int p = g_epack[e + 1];
            int si = (p & 0xFFFFF) * 64 + lane;
            pk = kv4[si];
            pv = kv4[si + 32];
            pr4 = s_rel[(p >> 20) * 32 + lane];
        }
        kk.x += rel.x; kk.y += rel.y; kk.z += rel.z; kk.w += rel.w;
        float pr = qr.x * kk.x + qr.y * kk.y + qr.z * kk.z + qr.w * kk.w;
        pr += __shfl_xor_sync(0xffffffffu, pr, 4);
        pr += __shfl_xor_sync(0xffffffffu, pr, 2);
        pr += __shfl_xor_sync(0xffffffffu, pr, 1);
        float score = pr * SCALE2F;                 // base-2 domain
        float nm = fmaxf(m, score);
        float cf = exp2f(m - nm);
        float w  = exp2f(score - nm);
        vv.x += rel.x; vv.y += rel.y; vv.z += rel.z; vv.w += rel.w;
        ss = ss * cf + w;
        acc.x = acc.x * cf + w * vv.x;
        acc.y = acc.y * cf + w * vv.y;
        acc.z = acc.z * cf + w * vv.z;
        acc.w = acc.w * cf + w * vv.w;
        m = nm;
    }

    float inv = 1.f / (ss + 1e-9f);
    float4 hi = ((const float4*)hin)[idx];
    float4 x;
    x.x = acc.x * inv + hi.x;
    x.y = acc.y * inv + hi.y;
    x.z = acc.z * inv + hi.z;
    x.w = acc.w * inv + hi.w;
    x.x = (x.x > 0.f) ? x.x : (__expf(x.x) - 1.f);
    x.y = (x.y > 0.f) ? x.y : (__expf(x.y) - 1.f);
    x.z = (x.z > 0.f) ? x.z : (__expf(x.z) - 1.f);
    x.w = (x.w > 0.f) ? x.w : (__expf(x.w) - 1.f);

    if (LAYER == 0) {
        ((float4*)g_h)[idx] = x;
    } else {
        // fused output head: dot over all 128 dims (full-warp reduce)
        float4 w4 = ((const float4*)Wout)[lane];
        float p = x.x * w4.x + x.y * w4.y + x.z * w4.z + x.w * w4.w;
        p += __shfl_xor_sync(0xffffffffu, p, 16);
        p += __shfl_xor_sync(0xffffffffu, p, 8);
        p += __shfl_xor_sync(0xffffffffu, p, 4);
        p += __shfl_xor_sync(0xffffffffu, p, 2);
        p += __shfl_xor_sync(0xffffffffu, p, 1);
        if (lane == 0) {
            float lg = p + bout[0];
            float sc = cent[gw] * gamma[0] + beta[0];
            float r = sc * lg;
            out[gw] = (r > 0.f) ? r : 0.f;
        }
    }
}

// ---------------- launch ------------------------------------------------------
extern "C" void kernel_launch(void* const* d_in, const int* in_sizes, int n_in,
                              void* d_out, int out_size) {
    const float* inputs  = (const float*)d_in[0];
    const int*   et      = (const int*)d_in[1];
    const int*   src     = (const int*)d_in[2];
    const int*   dst     = (const int*)d_in[3];
    const float* cent    = (const float*)d_in[4];
    const float* rel_emb = (const float*)d_in[5];
    const float* Wq      = (const float*)d_in[6];
    const float* bq      = (const float*)d_in[7];
    const float* Wk      = (const float*)d_in[8];
    const float* bk      = (const float*)d_in[9];
    const float* Wv      = (const float*)d_in[10];
    const float* bv      = (const float*)d_in[11];
    const float* We      = (const float*)d_in[12];
    const float* be      = (const float*)d_in[13];
    const float* Wout    = (const float*)d_in[14];
    const float* bout    = (const float*)d_in[15];
    const float* gamma   = (const float*)d_in[16];
    const float* beta    = (const float*)d_in[17];
    float* out = (float*)d_out;

    // side stream + events, created once OUTSIDE capture (correctness call runs first)
    static cudaStream_t s_side = nullptr;
    static cudaEvent_t  s_fork = nullptr, s_join = nullptr;
    if (s_side == nullptr) {
        cudaStreamCreateWithFlags(&s_side, cudaStreamNonBlocking);
        cudaEventCreateWithFlags(&s_fork, cudaEventDisableTiming);
        cudaEventCreateWithFlags(&s_join, cudaEventDisableTiming);
    }

    // fork: CSR build + rel projections run concurrently with layer-0 GEMMs
    cudaEventRecord(s_fork, 0);
    cudaStreamWaitEvent(s_side, s_fork, 0);
    k_zero_rowptr<<<(N_NODES + 256) / 256, 256, 0, s_side>>>();
    k_hist<<<(N_EDGES + 255) / 256, 256, 0, s_side>>>(dst);
    k_scan<<<1, 1024, 0, s_side>>>();
    k_scatter<<<(N_EDGES + 255) / 256, 256, 0, s_side>>>(src, dst, et);
    k_relproj<<<NLAYER * RNUM, FDIM, 0, s_side>>>(rel_emb, We, be);
    cudaEventRecord(s_join, s_side);

    int gemm_blocks = (N_NODES + 63) / 64;
    int attn_blocks = (N_NODES * 32 + 255) / 256;

    // layer 0
    k_gemm<0><<<gemm_blocks, 256>>>(inputs, 0, Wq, bq);
    k_gemm<1><<<gemm_blocks, 256>>>(inputs, 0, Wk, bk);
    k_gemm<2><<<gemm_blocks, 256>>>(inputs, 0, Wv, bv);
    cudaStreamWaitEvent(0, s_join, 0);     // CSR + rel ready
    k_attn<0><<<attn_blocks, 256>>>(inputs, Wout, bout, cent, gamma, beta, out);

    // layer 1 (+ fused output head)
    int wo = FDIM * FDIM, bo = FDIM;
    k_gemm<0><<<gemm_blocks, 256>>>(inputs, 1, Wq + wo, bq + bo);
    k_gemm<1><<<gemm_blocks, 256>>>(inputs, 1, Wk + wo, bk + bo);
    k_gemm<2><<<gemm_blocks, 256>>>(inputs, 1, Wv + wo, bv + bo);
    k_attn<1><<<attn_blocks, 256>>>(inputs, Wout, bout, cent, gamma, beta, out);
}

// round 9
// speedup vs baseline: 2.1944x; 1.0123x over previous
#include <cuda_runtime.h>
#include <cuda_fp16.h>
#include <cstdint>
#include <math.h>

#define N_NODES 50000
#define N_EDGES 800000
#define FDIM    128
#define RNUM    11
#define NLAYER  2
#define SCALE2F (0.17677669529663687f * 1.4426950408889634f)   // (1/sqrt32)*log2(e)

typedef unsigned long long ull;

// ---------------- scratch (device globals; no allocation allowed) -------------
__device__ float  g_h[N_NODES * FDIM];
__device__ float  g_q[N_NODES * FDIM];
__device__ __half g_kvh[N_NODES * 2 * FDIM];   // per node: 128 k halves, 128 v halves
__device__ float  g_rel[NLAYER * RNUM * FDIM];
__device__ int    g_rowptr[N_NODES + 1];
__device__ int    g_cursor[N_NODES];
__device__ int    g_epack[N_EDGES];            // src | (edge_type << 20)

// ---------------- f32x2 helpers ----------------------------------------------
__device__ __forceinline__ ull fma2(ull a, ull b, ull c) {
    ull d;
    asm("fma.rn.f32x2 %0, %1, %2, %3;" : "=l"(d) : "l"(a), "l"(b), "l"(c));
    return d;
}
__device__ __forceinline__ ull dup2(float b) {
    ull d;
    asm("mov.b64 %0, {%1, %1};" : "=l"(d) : "f"(b));
    return d;
}
__device__ __forceinline__ float2 unpack2(ull a) {
    float2 r;
    asm("mov.b64 {%0, %1}, %2;" : "=f"(r.x), "=f"(r.y) : "l"(a));
    return r;
}

// ---------------- CSR build ---------------------------------------------------
__global__ void k_zero_rowptr() {
    int i = blockIdx.x * blockDim.x + threadIdx.x;
    if (i <= N_NODES) g_rowptr[i] = 0;
}
__global__ void k_hist(const int* __restrict__ dst) {
    int e = blockIdx.x * blockDim.x + threadIdx.x;
    if (e < N_EDGES) atomicAdd(&g_rowptr[dst[e] + 1], 1);
}
__global__ void __launch_bounds__(1024) k_scan() {
    __shared__ int s_w[32];
    __shared__ int s_carry;
    int tid = threadIdx.x, lane = tid & 31, wid = tid >> 5;
    if (tid == 0) s_carry = 0;
    __syncthreads();
    const int n = N_NODES + 1;
    for (int base = 0; base < n; base += 1024) {
        int i = base + tid;
        int v = (i < n) ? g_rowptr[i] : 0;
        #pragma unroll
        for (int off = 1; off < 32; off <<= 1) {
            int t = __shfl_up_sync(0xffffffffu, v, off);
            if (lane >= off) v += t;
        }
        if (lane == 31) s_w[wid] = v;
        __syncthreads();
        if (wid == 0) {
            int s = s_w[lane];
            #pragma unroll
            for (int off = 1; off < 32; off <<= 1) {
                int t = __shfl_up_sync(0xffffffffu, s, off);
                if (lane >= off) s += t;
            }
            s_w[lane] = s;
        }
        __syncthreads();
        int res = v + (wid > 0 ? s_w[wid - 1] : 0) + s_carry;
        if (i < n) g_rowptr[i] = res;
        if (i < N_NODES) g_cursor[i] = res;
        __syncthreads();
        if (tid == 1023) s_carry = res;
        __syncthreads();
    }
}
__global__ void k_scatter(const int* __restrict__ src, const int* __restrict__ dst,
                          const int* __restrict__ et) {
    int e = blockIdx.x * blockDim.x + threadIdx.x;
    if (e < N_EDGES) {
        int slot = atomicAdd(&g_cursor[dst[e]], 1);
        g_epack[slot] = src[e] | (et[e] << 20);
    }
}

// ---------------- rel projection, both layers ---------------------------------
__global__ void k_relproj(const float* __restrict__ rel_emb,
                          const float* __restrict__ We,
                          const float* __restrict__ be) {
    int r = blockIdx.x % RNUM, l = blockIdx.x / RNUM;
    int o = threadIdx.x;
    const float* W = We + l * FDIM * FDIM;
    float acc = be[l * FDIM + o];
    #pragma unroll 4
    for (int f = 0; f < FDIM; f++)
        acc += rel_emb[r * FDIM + f] * W[f * FDIM + o];
    g_rel[(l * RNUM + r) * FDIM + o] = acc;
}

// ---------------- QKV GEMM with f32x2, BK=64: C = A[N,128] @ W + b ------------
// BM=64, BN=128, BK=64, 256 threads, thread tile 8x4 (acc packed over row pairs)
// SEL 0 -> g_q fp32; SEL 1 -> g_kvh k-half; SEL 2 -> g_kvh v-half (fp16 out)
template <int SEL>
__global__ void __launch_bounds__(256) k_gemm(const float* __restrict__ Aext, int layer,
                                              const float* __restrict__ W,
                                              const float* __restrict__ bias) {
    const float* A = layer ? g_h : Aext;

    extern __shared__ float smem[];
    float (*AsT)[68] = (float(*)[68])smem;               // [64][68] transposed
    float (*Bs)[128] = (float(*)[128])(smem + 64 * 68);  // [64][128]

    int tid = threadIdx.x;
    int ty = tid >> 5, tx = tid & 31;
    int rowBase = blockIdx.x * 64;

    ull accP[4][4];
    #pragma unroll
    for (int i = 0; i < 4; i++)
        #pragma unroll
        for (int j = 0; j < 4; j++) accP[i][j] = 0ull;

    for (int k0 = 0; k0 < FDIM; k0 += 64) {
        // A tile: 64 rows x 64 cols = 1024 float4, 4 per thread, store transposed
        #pragma unroll
        for (int t = 0; t < 4; t++) {
            int v = tid + t * 256;
            int r = v >> 4, c4 = v & 15;
            int grow = rowBase + r;
            float4 a = (grow < N_NODES)
                ? *(const float4*)(A + (size_t)grow * FDIM + k0 + c4 * 4)
                : make_float4(0.f, 0.f, 0.f, 0.f);
            AsT[c4 * 4 + 0][r] = a.x;
            AsT[c4 * 4 + 1][r] = a.y;
            AsT[c4 * 4 + 2][r] = a.z;
            AsT[c4 * 4 + 3][r] = a.w;
        }
        // B tile: 64 x 128 = 2048 float4, 8 per thread
        #pragma unroll
        for (int t = 0; t < 8; t++) {
            int v = tid + t * 256;
            int r = v >> 5, c4 = v & 31;
            *(float4*)(&Bs[r][c4 * 4]) = *(const float4*)(W + (k0 + r) * FDIM + c4 * 4);
        }
        __syncthreads();
        #pragma unroll 8
        for (int kk = 0; kk < 64; kk++) {
            ulonglong2 aA = *(const ulonglong2*)(&AsT[kk][ty * 8]);
            ulonglong2 aB = *(const ulonglong2*)(&AsT[kk][ty * 8 + 4]);
            float4 b = *(const float4*)(&Bs[kk][tx * 4]);
            ull aP[4] = {aA.x, aA.y, aB.x, aB.y};
            ull bd[4] = {dup2(b.x), dup2(b.y), dup2(b.z), dup2(b.w)};
            #pragma unroll
            for (int ip = 0; ip < 4; ip++)
                #pragma unroll
                for (int j = 0; j < 4; j++)
                    accP[ip][j] = fma2(aP[ip], bd[j], accP[ip][j]);
        }
        __syncthreads();
    }

    float4 bia = *(const float4*)(bias + tx * 4);
    #pragma unroll
    for (int ip = 0; ip < 4; ip++) {
        float2 c0 = unpack2(accP[ip][0]);
        float2 c1 = unpack2(accP[ip][1]);
        float2 c2 = unpack2(accP[ip][2]);
        float2 c3 = unpack2(accP[ip][3]);
        int r0 = rowBase + ty * 8 + 2 * ip;
        int r1 = r0 + 1;
        float4 o0 = {c0.x + bia.x, c1.x + bia.y, c2.x + bia.z, c3.x + bia.w};
        float4 o1 = {c0.y + bia.x, c1.y + bia.y, c2.y + bia.z, c3.y + bia.w};
        if (SEL == 0) {
            if (r0 < N_NODES) *(float4*)(g_q + (size_t)r0 * FDIM + tx * 4) = o0;
            if (r1 < N_NODES) *(float4*)(g_q + (size_t)r1 * FDIM + tx * 4) = o1;
        } else {
            __half* C = g_kvh + (SEL == 1 ? 0 : FDIM);
            if (r0 < N_NODES) {
                __half2 h01 = __floats2half2_rn(o0.x, o0.y);
                __half2 h23 = __floats2half2_rn(o0.z, o0.w);
                uint2 pk = {*(unsigned*)&h01, *(unsigned*)&h23};
                *(uint2*)(C + (size_t)r0 * 2 * FDIM + tx * 4) = pk;
            }
            if (r1 < N_NODES) {
                __half2 h01 = __floats2half2_rn(o1.x, o1.y);
                __half2 h23 = __floats2half2_rn(o1.z, o1.w);
                uint2 pk = {*(unsigned*)&h01, *(unsigned*)&h23};
                *(uint2*)(C + (size_t)r1 * 2 * FDIM + tx * 4) = pk;
            }
        }
    }
}

// ---------------- fused attention: warp per dst node, 8 lanes per head --------
// lane l owns features [4l,4l+4); k/v streamed in fp16; softmax in base-2 domain.
// LAYER 1 also computes the fused output head.
template <int LAYER>
__global__ void __launch_bounds__(256) k_attn(const float* __restrict__ inputs,
                                              const float* __restrict__ Wout,
                                              const float* __restrict__ bout,
                                              const float* __restrict__ cent,
                                              const float* __restrict__ gamma,
                                              const float* __restrict__ beta,
                                              float* __restrict__ out) {
    __shared__ float4 s_rel[RNUM * 32];
    {
        const float4* rel4 = (const float4*)(g_rel + LAYER * RNUM * FDIM);
        for (int i = threadIdx.x; i < RNUM * 32; i += 256) s_rel[i] = rel4[i];
    }
    __syncthreads();

    int gw = (blockIdx.x * 256 + threadIdx.x) >> 5;
    int lane = threadIdx.x & 31;
    if (gw >= N_NODES) return;

    const float* hin = LAYER ? g_h : inputs;
    const uint2* kvp = (const uint2*)g_kvh;     // 4 halves per uint2; 64 per node
    int idx = gw * 32 + lane;

    float4 qr = ((const float4*)g_q)[idx];
    float m = -INFINITY, ss = 0.f;
    float4 acc = make_float4(0.f, 0.f, 0.f, 0.f);

    int e0 = g_rowptr[gw], e1 = g_rowptr[gw + 1];
    uint2 pk, pv;
    float4 pr4;
    if (e0 < e1) {
        int p = g_epack[e0];
        int si = (p & 0xFFFFF) * 64 + lane;
        pk = kvp[si];
        pv = kvp[si + 32];
        pr4 = s_rel[(p >> 20) * 32 + lane];
    }
    for (int e = e0; e < e1; e++) {
        uint2 kr = pk, vr = pv;
        float4 rel = pr4;
        if (e + 1 < e1) {
            int p = g_epack[e + 1];
            int si = (p & 0xFFFFF) * 64 + lane;
            pk = kvp[si];
            pv = kvp[si + 32];
            pr4 = s_rel[(p >> 20) * 32 + lane];
        }
        float2 k01 = __half22float2(*(__half2*)&kr.x);
        float2 k23 = __half22float2(*(__half2*)&kr.y);
        float kx = k01.x + rel.x, ky = k01.y + rel.y;
        float kz = k23.x + rel.z, kw = k23.y + rel.w;
        float pr = qr.x * kx + qr.y * ky + qr.z * kz + qr.w * kw;
        pr += __shfl_xor_sync(0xffffffffu, pr, 4);
        pr += __shfl_xor_sync(0xffffffffu, pr, 2);
        pr += __shfl_xor_sync(0xffffffffu, pr, 1);
        float score = pr * SCALE2F;
        float nm = fmaxf(m, score);
        float cf = exp2f(m - nm);
        float w  = exp2f(score - nm);
        float2 v01 = __half22float2(*(__half2*)&vr.x);
        float2 v23 = __half22float2(*(__half2*)&vr.y);
        ss = ss * cf + w;
        acc.x = acc.x * cf + w * (v01.x + rel.x);
        acc.y = acc.y * cf + w * (v01.y + rel.y);
        acc.z = acc.z * cf + w * (v23.x + rel.z);
        acc.w = acc.w * cf + w * (v23.y + rel.w);
        m = nm;
    }

    float inv = 1.f / (ss + 1e-9f);
    float4 hi = ((const float4*)hin)[idx];
    float4 x;
    x.x = acc.x * inv + hi.x;
    x.y = acc.y * inv + hi.y;
    x.z = acc.z * inv + hi.z;
    x.w = acc.w * inv + hi.w;
    x.x = (x.x > 0.f) ? x.x : (__expf(x.x) - 1.f);
    x.y = (x.y > 0.f) ? x.y : (__expf(x.y) - 1.f);
    x.z = (x.z > 0.f) ? x.z : (__expf(x.z) - 1.f);
    x.w = (x.w > 0.f) ? x.w : (__expf(x.w) - 1.f);

    if (LAYER == 0) {
        ((float4*)g_h)[idx] = x;
    } else {
        float4 w4 = ((const float4*)Wout)[lane];
        float p = x.x * w4.x + x.y * w4.y + x.z * w4.z + x.w * w4.w;
        p += __shfl_xor_sync(0xffffffffu, p, 16);
        p += __shfl_xor_sync(0xffffffffu, p, 8);
        p += __shfl_xor_sync(0xffffffffu, p, 4);
        p += __shfl_xor_sync(0xffffffffu, p, 2);
        p += __shfl_xor_sync(0xffffffffu, p, 1);
        if (lane == 0) {
            float lg = p + bout[0];
            float sc = cent[gw] * gamma[0] + beta[0];
            float r = sc * lg;
            out[gw] = (r > 0.f) ? r : 0.f;
        }
    }
}

// ---------------- launch ------------------------------------------------------
extern "C" void kernel_launch(void* const* d_in, const int* in_sizes, int n_in,
                              void* d_out, int out_size) {
    const float* inputs  = (const float*)d_in[0];
    const int*   et      = (const int*)d_in[1];
    const int*   src     = (const int*)d_in[2];
    const int*   dst     = (const int*)d_in[3];
    const float* cent    = (const float*)d_in[4];
    const float* rel_emb = (const float*)d_in[5];
    const float* Wq      = (const float*)d_in[6];
    const float* bq      = (const float*)d_in[7];
    const float* Wk      = (const float*)d_in[8];
    const float* bk      = (const float*)d_in[9];
    const float* Wv      = (const float*)d_in[10];
    const float* bv      = (const float*)d_in[11];
    const float* We      = (const float*)d_in[12];
    const float* be      = (const float*)d_in[13];
    const float* Wout    = (const float*)d_in[14];
    const float* bout    = (const float*)d_in[15];
    const float* gamma   = (const float*)d_in[16];
    const float* beta    = (const float*)d_in[17];
    float* out = (float*)d_out;

    const int GEMM_SMEM = (64 * 68 + 64 * 128) * 4;   // 50176 bytes

    static cudaStream_t s_side = nullptr;
    static cudaEvent_t  s_fork = nullptr, s_join = nullptr;
    if (s_side == nullptr) {
        cudaStreamCreateWithFlags(&s_side, cudaStreamNonBlocking);
        cudaEventCreateWithFlags(&s_fork, cudaEventDisableTiming);
        cudaEventCreateWithFlags(&s_join, cudaEventDisableTiming);
        cudaFuncSetAttribute(k_gemm<0>, cudaFuncAttributeMaxDynamicSharedMemorySize, GEMM_SMEM);
        cudaFuncSetAttribute(k_gemm<1>, cudaFuncAttributeMaxDynamicSharedMemorySize, GEMM_SMEM);
        cudaFuncSetAttribute(k_gemm<2>, cudaFuncAttributeMaxDynamicSharedMemorySize, GEMM_SMEM);
    }

    // fork: CSR build + rel projections run concurrently with layer-0 GEMMs
    cudaEventRecord(s_fork, 0);
    cudaStreamWaitEvent(s_side, s_fork, 0);
    k_zero_rowptr<<<(N_NODES + 256) / 256, 256, 0, s_side>>>();
    k_hist<<<(N_EDGES + 255) / 256, 256, 0, s_side>>>(dst);
    k_scan<<<1, 1024, 0, s_side>>>();
    k_scatter<<<(N_EDGES + 255) / 256, 256, 0, s_side>>>(src, dst, et);
    k_relproj<<<NLAYER * RNUM, FDIM, 0, s_side>>>(rel_emb, We, be);
    cudaEventRecord(s_join, s_side);

    int gemm_blocks = (N_NODES + 63) / 64;
    int attn_blocks = (N_NODES * 32 + 255) / 256;

    // layer 0
    k_gemm<0><<<gemm_blocks, 256, GEMM_SMEM>>>(inputs, 0, Wq, bq);
    k_gemm<1><<<gemm_blocks, 256, GEMM_SMEM>>>(inputs, 0, Wk, bk);
    k_gemm<2><<<gemm_blocks, 256, GEMM_SMEM>>>(inputs, 0, Wv, bv);
    cudaStreamWaitEvent(0, s_join, 0);
    k_attn<0><<<attn_blocks, 256>>>(inputs, Wout, bout, cent, gamma, beta, out);

    // layer 1 (+ fused output head)
    int wo = FDIM * FDIM, bo = FDIM;
    k_gemm<0><<<gemm_blocks, 256, GEMM_SMEM>>>(inputs, 1, Wq + wo, bq + bo);
    k_gemm<1><<<gemm_blocks, 256, GEMM_SMEM>>>(inputs, 1, Wk + wo, bk + bo);
    k_gemm<2><<<gemm_blocks, 256, GEMM_SMEM>>>(inputs, 1, Wv + wo, bv + bo);
    k_attn<1><<<attn_blocks, 256>>>(inputs, Wout, bout, cent, gamma, beta, out);
}

// round 10
// speedup vs baseline: 3.4920x; 1.5913x over previous
#include <cuda_runtime.h>
#include <cuda_fp16.h>
#include <cstdint>
#include <math.h>

#define N_NODES 50000
#define N_EDGES 800000
#define FDIM    128
#define RNUM    11
#define NLAYER  2
#define NTILES  391                              // ceil(50000/128)
#define SCALE2F (0.17677669529663687f * 1.4426950408889634f)   // (1/sqrt32)*log2(e)

typedef unsigned long long ull;

// ---------------- scratch (device globals; no allocation allowed) -------------
__device__ float  g_h[N_NODES * FDIM];
__device__ float  g_q[N_NODES * FDIM];
__device__ __align__(16) __half g_kvh[N_NODES * 2 * FDIM]; // per node: 128 k, 128 v
__device__ __align__(16) __half g_wh[6 * FDIM * FDIM];     // fp16 W, [layer*3+sel][k][n]
__device__ float  g_rel[NLAYER * RNUM * FDIM];
__device__ int    g_rowptr[N_NODES + 1];
__device__ int    g_cursor[N_NODES];
__device__ int    g_epack[N_EDGES];              // src | (edge_type << 20)

// ---------------- PTX helpers --------------------------------------------------
__device__ __forceinline__ unsigned smem_u32(const void* p) {
    unsigned a;
    asm("{ .reg .u64 t; cvta.to.shared.u64 t, %1; cvt.u32.u64 %0, t; }" : "=r"(a) : "l"(p));
    return a;
}
__device__ __forceinline__ void ldsm4(unsigned* r, unsigned addr) {
    asm volatile("ldmatrix.sync.aligned.m8n8.x4.shared.b16 {%0,%1,%2,%3}, [%4];"
                 : "=r"(r[0]), "=r"(r[1]), "=r"(r[2]), "=r"(r[3]) : "r"(addr));
}
__device__ __forceinline__ void ldsm4t(unsigned* r, unsigned addr) {
    asm volatile("ldmatrix.sync.aligned.m8n8.x4.trans.shared.b16 {%0,%1,%2,%3}, [%4];"
                 : "=r"(r[0]), "=r"(r[1]), "=r"(r[2]), "=r"(r[3]) : "r"(addr));
}
__device__ __forceinline__ void mma16816(float* d, const unsigned* a, const unsigned* b) {
    asm volatile(
        "mma.sync.aligned.m16n8k16.row.col.f32.f16.f16.f32 "
        "{%0,%1,%2,%3}, {%4,%5,%6,%7}, {%8,%9}, {%0,%1,%2,%3};"
        : "+f"(d[0]), "+f"(d[1]), "+f"(d[2]), "+f"(d[3])
        : "r"(a[0]), "r"(a[1]), "r"(a[2]), "r"(a[3]), "r"(b[0]), "r"(b[1]));
}

// ---------------- CSR build ---------------------------------------------------
__global__ void k_zero_rowptr() {
    int i = blockIdx.x * blockDim.x + threadIdx.x;
    if (i <= N_NODES) g_rowptr[i] = 0;
}
__global__ void k_hist(const int* __restrict__ dst) {
    int e = blockIdx.x * blockDim.x + threadIdx.x;
    if (e < N_EDGES) atomicAdd(&g_rowptr[dst[e] + 1], 1);
}
__global__ void __launch_bounds__(1024) k_scan() {
    __shared__ int s_w[32];
    __shared__ int s_carry;
    int tid = threadIdx.x, lane = tid & 31, wid = tid >> 5;
    if (tid == 0) s_carry = 0;
    __syncthreads();
    const int n = N_NODES + 1;
    for (int base = 0; base < n; base += 1024) {
        int i = base + tid;
        int v = (i < n) ? g_rowptr[i] : 0;
        #pragma unroll
        for (int off = 1; off < 32; off <<= 1) {
            int t = __shfl_up_sync(0xffffffffu, v, off);
            if (lane >= off) v += t;
        }
        if (lane == 31) s_w[wid] = v;
        __syncthreads();
        if (wid == 0) {
            int s = s_w[lane];
            #pragma unroll
            for (int off = 1; off < 32; off <<= 1) {
                int t = __shfl_up_sync(0xffffffffu, s, off);
                if (lane >= off) s += t;
            }
            s_w[lane] = s;
        }
        __syncthreads();
        int res = v + (wid > 0 ? s_w[wid - 1] : 0) + s_carry;
        if (i < n) g_rowptr[i] = res;
        if (i < N_NODES) g_cursor[i] = res;
        __syncthreads();
        if (tid == 1023) s_carry = res;
        __syncthreads();
    }
}
__global__ void k_scatter(const int* __restrict__ src, const int* __restrict__ dst,
                          const int* __restrict__ et) {
    int e = blockIdx.x * blockDim.x + threadIdx.x;
    if (e < N_EDGES) {
        int slot = atomicAdd(&g_cursor[dst[e]], 1);
        g_epack[slot] = src[e] | (et[e] << 20);
    }
}

// ---------------- rel projection, both layers ---------------------------------
__global__ void k_relproj(const float* __restrict__ rel_emb,
                          const float* __restrict__ We,
                          const float* __restrict__ be) {
    int r = blockIdx.x % RNUM, l = blockIdx.x / RNUM;
    int o = threadIdx.x;
    const float* W = We + l * FDIM * FDIM;
    float acc = be[l * FDIM + o];
    #pragma unroll 4
    for (int f = 0; f < FDIM; f++)
        acc += rel_emb[r * FDIM + f] * W[f * FDIM + o];
    g_rel[(l * RNUM + r) * FDIM + o] = acc;
}

// ---------------- prep: convert 6 weight matrices to fp16 ---------------------
__global__ void k_prepw(const float* __restrict__ Wq, const float* __restrict__ Wk,
                        const float* __restrict__ Wv) {
    int i = blockIdx.x * 256 + threadIdx.x;      // 6*16384 elements
    int mat = i >> 14, r = i & 16383;
    int sel = mat % 3, layer = mat / 3;
    const float* W = (sel == 0 ? Wq : sel == 1 ? Wk : Wv) + layer * FDIM * FDIM;
    g_wh[i] = __float2half_rn(W[r]);
}

// ---------------- fused QKV GEMM via HMMA (m16n8k16, fp16 in, fp32 acc) -------
// block: 256 threads = 8 warps (4 m x 2 n), tile 128x128; loops 3 weight mats.
__global__ void __launch_bounds__(256) k_gemm_qkv(const float* __restrict__ Aext, int layer,
                                                  const float* __restrict__ bq,
                                                  const float* __restrict__ bk,
                                                  const float* __restrict__ bv) {
    const float* A = layer ? g_h : Aext;
    extern __shared__ __half sm[];
    __half (*As)[136] = (__half(*)[136])sm;               // [128][136]
    __half (*Bs)[136] = (__half(*)[136])(sm + 128 * 136); // [128][136], [k][n]

    int tid = threadIdx.x, wid = tid >> 5, lane = tid & 31;
    int wm = wid & 3, wn = wid >> 2;
    int rowBase = blockIdx.x * 128;
    unsigned sA = smem_u32(As), sB = smem_u32(Bs);

    // load A tile (fp32 -> fp16)
    #pragma unroll
    for (int t = 0; t < 16; t++) {
        int v = tid + t * 256;
        int r = v >> 5, c4 = v & 31;
        int grow = rowBase + r;
        float4 a = (grow < N_NODES)
            ? *(const float4*)(A + (size_t)grow * FDIM + c4 * 4)
            : make_float4(0.f, 0.f, 0.f, 0.f);
        *(__half2*)&As[r][c4 * 4]     = __floats2half2_rn(a.x, a.y);
        *(__half2*)&As[r][c4 * 4 + 2] = __floats2half2_rn(a.z, a.w);
    }

    unsigned quad = lane >> 3, lr = lane & 7;
    int g = lane >> 2, tg = lane & 3;

    #pragma unroll 1
    for (int sel = 0; sel < 3; sel++) {
        __syncthreads();          // As ready (sel 0) / prev sel done with Bs
        {
            const __half* Wsrc = g_wh + (size_t)(layer * 3 + sel) * 16384;
            #pragma unroll
            for (int t = 0; t < 8; t++) {
                int v = tid + t * 256;
                int r = v >> 4, c8 = v & 15;
                *(uint4*)&Bs[r][c8 * 8] = *(const uint4*)(Wsrc + r * FDIM + c8 * 8);
            }
        }
        __syncthreads();

        float acc[2][8][4];
        #pragma unroll
        for (int i = 0; i < 2; i++)
            #pragma unroll
            for (int j = 0; j < 8; j++)
                #pragma unroll
                for (int c = 0; c < 4; c++) acc[i][j][c] = 0.f;

        #pragma unroll
        for (int ks = 0; ks < 8; ks++) {
            int k0 = ks * 16;
            unsigned af[2][4], bf[4][4];
            #pragma unroll
            for (int i = 0; i < 2; i++) {
                int arow = wm * 32 + i * 16 + ((quad & 1) << 3) + lr;
                int acol = k0 + ((quad >> 1) << 3);
                ldsm4(af[i], sA + (arow * 136 + acol) * 2);
            }
            #pragma unroll
            for (int j2 = 0; j2 < 4; j2++) {
                int brow = k0 + ((quad & 1) << 3) + lr;
                int bcol = wn * 64 + j2 * 16 + ((quad >> 1) << 3);
                ldsm4t(bf[j2], sB + (brow * 136 + bcol) * 2);
            }
            #pragma unroll
            for (int i = 0; i < 2; i++)
                #pragma unroll
                for (int j = 0; j < 8; j++)
                    mma16816(acc[i][j], af[i], &bf[j >> 1][(j & 1) * 2]);
        }

        // epilogue
        const float* bias = (sel == 0 ? bq : sel == 1 ? bk : bv) + layer * FDIM;
        #pragma unroll
        for (int i = 0; i < 2; i++) {
            int r0 = rowBase + wm * 32 + i * 16 + g;
            int r1 = r0 + 8;
            #pragma unroll
            for (int j = 0; j < 8; j++) {
                int col = wn * 64 + j * 8 + tg * 2;
                float2 b2 = *(const float2*)(bias + col);
                float d0 = acc[i][j][0] + b2.x, d1 = acc[i][j][1] + b2.y;
                float d2 = acc[i][j][2] + b2.x, d3 = acc[i][j][3] + b2.y;
                if (sel == 0) {
                    if (r0 < N_NODES) *(float2*)(g_q + (size_t)r0 * FDIM + col) = make_float2(d0, d1);
                    if (r1 < N_NODES) *(float2*)(g_q + (size_t)r1 * FDIM + col) = make_float2(d2, d3);
                } else {
                    int off = (sel == 1) ? 0 : FDIM;
                    if (r0 < N_NODES)
                        *(__half2*)(g_kvh + (size_t)r0 * 2 * FDIM + off + col) = __floats2half2_rn(d0, d1);
                    if (r1 < N_NODES)
                        *(__half2*)(g_kvh + (size_t)r1 * 2 * FDIM + off + col) = __floats2half2_rn(d2, d3);
                }
            }
        }
    }
}

// ---------------- fused attention: warp per dst node, 8 lanes per head --------
// lane l owns features [4l,4l+4); k/v streamed fp16; softmax in base-2 domain.
// LAYER 1 also computes the fused output head.
template <int LAYER>
__global__ void __launch_bounds__(256) k_attn(const float* __restrict__ inputs,
                                              const float* __restrict__ Wout,
                                              const float* __restrict__ bout,
                                              const float* __restrict__ cent,
                                              const float* __restrict__ gamma,
                                              const float* __restrict__ beta,
                                              float* __restrict__ out) {
    __shared__ float4 s_rel[RNUM * 32];
    {
        const float4* rel4 = (const float4*)(g_rel + LAYER * RNUM * FDIM);
        for (int i = threadIdx.x; i < RNUM * 32; i += 256) s_rel[i] = rel4[i];
    }
    __syncthreads();

    int gw = (blockIdx.x * 256 + threadIdx.x) >> 5;
    int lane = threadIdx.x & 31;
    if (gw >= N_NODES) return;

    const float* hin = LAYER ? g_h : inputs;
    const uint2* kvp = (const uint2*)g_kvh;     // 4 halves per uint2; 64 per node
    int idx = gw * 32 + lane;

    float4 qr = ((const float4*)g_q)[idx];
    float m = -INFINITY, ss = 0.f;
    float4 acc = make_float4(0.f, 0.f, 0.f, 0.f);

    int e0 = g_rowptr[gw], e1 = g_rowptr[gw + 1];
    uint2 pk, pv;
    float4 pr4;
    if (e0 < e1) {
        int p = g_epack[e0];
        int si = (p & 0xFFFFF) * 64 + lane;
        pk = kvp[si];
        pv = kvp[si + 32];
        pr4 = s_rel[(p >> 20) * 32 + lane];
    }
    for (int e = e0; e < e1; e++) {
        uint2 kr = pk, vr = pv;
        float4 rel = pr4;
        if (e + 1 < e1) {
            int p = g_epack[e + 1];
            int si = (p & 0xFFFFF) * 64 + lane;
            pk = kvp[si];
            pv = kvp[si + 32];
            pr4 = s_rel[(p >> 20) * 32 + lane];
        }
        float2 k01 = __half22float2(*(__half2*)&kr.x);
        float2 k23 = __half22float2(*(__half2*)&kr.y);
        float kx = k01.x + rel.x, ky = k01.y + rel.y;
        float kz = k23.x + rel.z, kw = k23.y + rel.w;
        float pr = qr.x * kx + qr.y * ky + qr.z * kz + qr.w * kw;
        pr += __shfl_xor_sync(0xffffffffu, pr, 4);
        pr += __shfl_xor_sync(0xffffffffu, pr, 2);
        pr += __shfl_xor_sync(0xffffffffu, pr, 1);
        float score = pr * SCALE2F;
        float nm = fmaxf(m, score);
        float cf = exp2f(m - nm);
        float w  = exp2f(score - nm);
        float2 v01 = __half22float2(*(__half2*)&vr.x);
        float2 v23 = __half22float2(*(__half2*)&vr.y);
        ss = ss * cf + w;
        acc.x = acc.x * cf + w * (v01.x + rel.x);
        acc.y = acc.y * cf + w * (v01.y + rel.y);
        acc.z = acc.z * cf + w * (v23.x + rel.z);
        acc.w = acc.w * cf + w * (v23.y + rel.w);
        m = nm;
    }

    float inv = 1.f / (ss + 1e-9f);
    float4 hi = ((const float4*)hin)[idx];
    float4 x;
    x.x = acc.x * inv + hi.x;
    x.y = acc.y * inv + hi.y;
    x.z = acc.z * inv + hi.z;
    x.w = acc.w * inv + hi.w;
    x.x = (x.x > 0.f) ? x.x : (__expf(x.x) - 1.f);
    x.y = (x.y > 0.f) ? x.y : (__expf(x.y) - 1.f);
    x.z = (x.z > 0.f) ? x.z : (__expf(x.z) - 1.f);
    x.w = (x.w > 0.f) ? x.w : (__expf(x.w) - 1.f);

    if (LAYER == 0) {
        ((float4*)g_h)[idx] = x;
    } else {
        float4 w4 = ((const float4*)Wout)[lane];
        float p = x.x * w4.x + x.y * w4.y + x.z * w4.z + x.w * w4.w;
        p += __shfl_xor_sync(0xffffffffu, p, 16);
        p += __shfl_xor_sync(0xffffffffu, p, 8);
        p += __shfl_xor_sync(0xffffffffu, p, 4);
        p += __shfl_xor_sync(0xffffffffu, p, 2);
        p += __shfl_xor_sync(0xffffffffu, p, 1);
        if (lane == 0) {
            float lg = p + bout[0];
            float sc = cent[gw] * gamma[0] + beta[0];
            float r = sc * lg;
            out[gw] = (r > 0.f) ? r : 0.f;
        }
    }
}

// ---------------- launch ------------------------------------------------------
extern "C" void kernel_launch(void* const* d_in, const int* in_sizes, int n_in,
                              void* d_out, int out_size) {
    const float* inputs  = (const float*)d_in[0];
    const int*   et      = (const int*)d_in[1];
    const int*   src     = (const int*)d_in[2];
    const int*   dst     = (const int*)d_in[3];
    const float* cent    = (const float*)d_in[4];
    const float* rel_emb = (const float*)d_in[5];
    const float* Wq      = (const float*)d_in[6];
    const float* bq      = (const float*)d_in[7];
    const float* Wk      = (const float*)d_in[8];
    const float* bk      = (const float*)d_in[9];
    const float* Wv      = (const float*)d_in[10];
    const float* bv      = (const float*)d_in[11];
    const float* We      = (const float*)d_in[12];
    const float* be      = (const float*)d_in[13];
    const float* Wout    = (const float*)d_in[14];
    const float* bout    = (const float*)d_in[15];
    const float* gamma   = (const float*)d_in[16];
    const float* beta    = (const float*)d_in[17];
    float* out = (float*)d_out;

    const int GEMM_SMEM = 2 * 128 * 136 * 2;   // 69632 bytes

    static cudaStream_t s1 = nullptr, s2 = nullptr;
    static cudaEvent_t ev_fork = nullptr, ev_prep = nullptr, ev_rel = nullptr, ev_csr = nullptr;
    if (s1 == nullptr) {
        cudaStreamCreateWithFlags(&s1, cudaStreamNonBlocking);
        cudaStreamCreateWithFlags(&s2, cudaStreamNonBlocking);
        cudaEventCreateWithFlags(&ev_fork, cudaEventDisableTiming);
        cudaEventCreateWithFlags(&ev_prep, cudaEventDisableTiming);
        cudaEventCreateWithFlags(&ev_rel, cudaEventDisableTiming);
        cudaEventCreateWithFlags(&ev_csr, cudaEventDisableTiming);
        cudaFuncSetAttribute(k_gemm_qkv, cudaFuncAttributeMaxDynamicSharedMemorySize, GEMM_SMEM);
    }

    cudaEventRecord(ev_fork, 0);

    // s1: W fp16 conversion, then rel projections
    cudaStreamWaitEvent(s1, ev_fork, 0);
    k_prepw<<<(6 * FDIM * FDIM) / 256, 256, 0, s1>>>(Wq, Wk, Wv);
    cudaEventRecord(ev_prep, s1);
    k_relproj<<<NLAYER * RNUM, FDIM, 0, s1>>>(rel_emb, We, be);
    cudaEventRecord(ev_rel, s1);

    // s2: CSR build
    cudaStreamWaitEvent(s2, ev_fork, 0);
    k_zero_rowptr<<<(N_NODES + 256) / 256, 256, 0, s2>>>();
    k_hist<<<(N_EDGES + 255) / 256, 256, 0, s2>>>(dst);
    k_scan<<<1, 1024, 0, s2>>>();
    k_scatter<<<(N_EDGES + 255) / 256, 256, 0, s2>>>(src, dst, et);
    cudaEventRecord(ev_csr, s2);

    int attn_blocks = (N_NODES * 32 + 255) / 256;

    // layer 0
    cudaStreamWaitEvent(0, ev_prep, 0);
    k_gemm_qkv<<<NTILES, 256, GEMM_SMEM>>>(inputs, 0, bq, bk, bv);
    cudaStreamWaitEvent(0, ev_csr, 0);
    cudaStreamWaitEvent(0, ev_rel, 0);
    k_attn<0><<<attn_blocks, 256>>>(inputs, Wout, bout, cent, gamma, beta, out);

    // layer 1 (+ fused output head)
    k_gemm_qkv<<<NTILES, 256, GEMM_SMEM>>>(inputs, 1, bq, bk, bv);
    k_attn<1><<<attn_blocks, 256>>>(inputs, Wout, bout, cent, gamma, beta, out);
}